// round 15
// baseline (speedup 1.0000x reference)
#include <cuda_runtime.h>
#include <cuda_bf16.h>
#include <cstdint>

#define V_DIM 128
#define N_ROWS 16384
#define WARPS_PER_BLOCK 8
#define THREADS_PER_BLOCK (WARPS_PER_BLOCK * 32)   // 256
#define ROWS_PER_WARP 2
#define ROWS_PER_BLOCK (WARPS_PER_BLOCK * ROWS_PER_WARP)   // 16
#define N_BLOCKS (N_ROWS / ROWS_PER_BLOCK)      // 1024

// Scratch (no device allocation allowed)
__device__ unsigned long long g_sum = 0ULL;     // fixed-point (x 2^32) total
__device__ int g_ticket = 0;

__global__ __launch_bounds__(THREADS_PER_BLOCK)
void fused_loss_kernel(const float* __restrict__ logits,
                       const float* __restrict__ targets,
                       float* __restrict__ out)
{
    __shared__ float s_warp[WARPS_PER_BLOCK];

    const int lane = threadIdx.x & 31;
    const int wid  = threadIdx.x >> 5;
    // 32-bit addressing (arrays are 8MB)
    const unsigned row0 = (blockIdx.x * WARPS_PER_BLOCK + wid) * ROWS_PER_WARP;
    const unsigned e0   = row0 * V_DIM + lane * 4;

    // ---- Front-batched loads: 2 rows x (logits,targets), float4 per lane ----
    float4 xv0 = *reinterpret_cast<const float4*>(logits  + e0);
    float4 tv0 = *reinterpret_cast<const float4*>(targets + e0);
    float4 xv1 = *reinterpret_cast<const float4*>(logits  + e0 + V_DIM);
    float4 tv1 = *reinterpret_cast<const float4*>(targets + e0 + V_DIM);

    float xs[2][4] = {{xv0.x, xv0.y, xv0.z, xv0.w}, {xv1.x, xv1.y, xv1.z, xv1.w}};
    float ts[2][4] = {{tv0.x, tv0.y, tv0.z, tv0.w}, {tv1.x, tv1.y, tv1.z, tv1.w}};

    // ---- Hoist all 8 ballots (VOTE latency overlaps the FMA chains below) ----
    unsigned m[2][4];
#pragma unroll
    for (int r = 0; r < 2; r++)
#pragma unroll
        for (int i = 0; i < 4; i++)
            m[r][i] = __ballot_sync(0xffffffffu, ts[r][i] > 0.5f);

    // ---- BCE pieces with split accumulators (2x ILP on the serial chains) ----
    float base0 = 0.0f, base1 = 0.0f;
    float prod0 = 1.0f, prod1 = 1.0f;   // each <= 2^8 over 8 factors
#pragma unroll
    for (int i = 0; i < 4; i++) {
        base0 += fmaxf(xs[0][i], 0.0f);
        base0  = fmaf(-xs[0][i], ts[0][i], base0);
        prod0 *= (1.0f + __expf(-fabsf(xs[0][i])));
        base1 += fmaxf(xs[1][i], 0.0f);
        base1  = fmaf(-xs[1][i], ts[1][i], base1);
        prod1 *= (1.0f + __expf(-fabsf(xs[1][i])));
    }

    // ---- c[r][i]: arithmetic self-exclusion (positives -> ~ -1e30) ----
    float c0[4], c1[4];
#pragma unroll
    for (int i = 0; i < 4; i++) {
        c0[i] = fmaf(ts[0][i], -1.0e30f, 1.0f + xs[0][i]);
        c1[i] = fmaf(ts[1][i], -1.0e30f, 1.0f + xs[1][i]);
    }

    // ---- Hinge: row0/row1 interleaved shuffle-broadcast (overlapped SHFL) ----
    float h0 = 0.0f, h1 = 0.0f, h2 = 0.0f, h3 = 0.0f;
#pragma unroll
    for (int i = 0; i < 4; i++) {
        unsigned m0 = m[0][i], m1 = m[1][i];
        while (m0 | m1) {                                   // warp-uniform
            bool has0 = (m0 != 0), has1 = (m1 != 0);
            float pv0 = 0.0f, pv1 = 0.0f;
            if (has0) {                                     // uniform branch
                int s0 = __ffs(m0) - 1; m0 &= m0 - 1;
                pv0 = __shfl_sync(0xffffffffu, xs[0][i], s0);
            }
            if (has1) {                                     // uniform branch
                int s1 = __ffs(m1) - 1; m1 &= m1 - 1;
                pv1 = __shfl_sync(0xffffffffu, xs[1][i], s1);
            }
            if (has0) {
                h0 += fmaxf(c0[0] - pv0, 0.0f);
                h1 += fmaxf(c0[1] - pv0, 0.0f);
                h2 += fmaxf(c0[2] - pv0, 0.0f);
                h3 += fmaxf(c0[3] - pv0, 0.0f);
            }
            if (has1) {
                h0 += fmaxf(c1[0] - pv1, 0.0f);
                h1 += fmaxf(c1[1] - pv1, 0.0f);
                h2 += fmaxf(c1[2] - pv1, 0.0f);
                h3 += fmaxf(c1[3] - pv1, 0.0f);
            }
        }
    }

    // One MUFU log per thread (prod0*prod1 <= 2^16: fp32-safe)
    float bce = (base0 + base1) + __logf(prod0 * prod1);
    float v = 0.7f * bce + 0.3f * ((h0 + h1) + (h2 + h3));

    // ---- Warp reduce ----
#pragma unroll
    for (int o = 16; o > 0; o >>= 1)
        v += __shfl_xor_sync(0xffffffffu, v, o);
    if (lane == 0) s_warp[wid] = v;
    __syncthreads();

    // ---- Block reduce (warp 0) + exact fixed-point atomic accumulate ----
    if (wid == 0) {
        float s = (lane < WARPS_PER_BLOCK) ? s_warp[lane] : 0.0f;
#pragma unroll
        for (int o = 16; o > 0; o >>= 1)
            s += __shfl_xor_sync(0xffffffffu, s, o);
        if (lane == 0) {
            // s >= 0; 2^32 fixed-point: exact integer accumulation => deterministic
            unsigned long long q =
                (unsigned long long)__double2ll_rn((double)s * 4294967296.0);
            atomicAdd(&g_sum, q);
            int t = atomicAdd(&g_ticket, 1);
            if (t == N_BLOCKS - 1) {
                unsigned long long total = atomicAdd(&g_sum, 0ULL);
                double d = (double)(long long)total * (1.0 / 4294967296.0);
                out[0] = (float)(d / ((double)V_DIM * (double)N_ROWS));
                g_sum = 0ULL;     // reset for next graph replay
                g_ticket = 0;
            }
        }
    }
}

extern "C" void kernel_launch(void* const* d_in, const int* in_sizes, int n_in,
                              void* d_out, int out_size)
{
    const float* logits  = (const float*)d_in[0];
    const float* targets = (const float*)d_in[1];
    float* out = (float*)d_out;

    fused_loss_kernel<<<N_BLOCKS, THREADS_PER_BLOCK>>>(logits, targets, out);
}

// round 16
// speedup vs baseline: 1.0570x; 1.0570x over previous
#include <cuda_runtime.h>
#include <cuda_bf16.h>
#include <cstdint>

#define V_DIM 128
#define N_ROWS 16384
#define WARPS_PER_BLOCK 8
#define THREADS_PER_BLOCK (WARPS_PER_BLOCK * 32)   // 256
#define ROWS_PER_WARP 2
#define ROWS_PER_BLOCK (WARPS_PER_BLOCK * ROWS_PER_WARP)   // 16
#define N_BLOCKS (N_ROWS / ROWS_PER_BLOCK)      // 1024

// Scratch (no device allocation allowed)
__device__ unsigned long long g_sum = 0ULL;     // fixed-point (x 2^32) total
__device__ int g_ticket = 0;

__global__ __launch_bounds__(THREADS_PER_BLOCK)
void fused_loss_kernel(const float* __restrict__ logits,
                       const float* __restrict__ targets,
                       float* __restrict__ out)
{
    __shared__ float s_warp[WARPS_PER_BLOCK];

    const int lane = threadIdx.x & 31;
    const int wid  = threadIdx.x >> 5;
    // 32-bit addressing (arrays are 8MB)
    const unsigned row0 = (blockIdx.x * WARPS_PER_BLOCK + wid) * ROWS_PER_WARP;
    const unsigned e0   = row0 * V_DIM + lane * 4;

    // ---- Front-batched loads: 2 rows x (logits,targets), float4 per lane ----
    float4 xv0 = *reinterpret_cast<const float4*>(logits  + e0);
    float4 tv0 = *reinterpret_cast<const float4*>(targets + e0);
    float4 xv1 = *reinterpret_cast<const float4*>(logits  + e0 + V_DIM);
    float4 tv1 = *reinterpret_cast<const float4*>(targets + e0 + V_DIM);

    float xs[2][4] = {{xv0.x, xv0.y, xv0.z, xv0.w}, {xv1.x, xv1.y, xv1.z, xv1.w}};
    float ts[2][4] = {{tv0.x, tv0.y, tv0.z, tv0.w}, {tv1.x, tv1.y, tv1.z, tv1.w}};

    // ---- Hoist all 8 ballots (VOTE latency overlaps the FMA chains below) ----
    unsigned m[2][4];
#pragma unroll
    for (int r = 0; r < 2; r++)
#pragma unroll
        for (int i = 0; i < 4; i++)
            m[r][i] = __ballot_sync(0xffffffffu, ts[r][i] > 0.5f);

    // ---- BCE pieces with split accumulators (2x ILP on the serial chains) ----
    float base0 = 0.0f, base1 = 0.0f;
    float prod0 = 1.0f, prod1 = 1.0f;   // each <= 2^8 over 8 factors
#pragma unroll
    for (int i = 0; i < 4; i++) {
        base0 += fmaxf(xs[0][i], 0.0f);
        base0  = fmaf(-xs[0][i], ts[0][i], base0);
        prod0 *= (1.0f + __expf(-fabsf(xs[0][i])));
        base1 += fmaxf(xs[1][i], 0.0f);
        base1  = fmaf(-xs[1][i], ts[1][i], base1);
        prod1 *= (1.0f + __expf(-fabsf(xs[1][i])));
    }

    // ---- Hinge: shuffle-broadcast of positives; arithmetic self-exclusion ----
    float h0 = 0.0f, h1 = 0.0f;
#pragma unroll
    for (int r = 0; r < 2; r++) {
        float c[4];
#pragma unroll
        for (int i = 0; i < 4; i++)
            c[i] = fmaf(ts[r][i], -1.0e30f, 1.0f + xs[r][i]);
#pragma unroll
        for (int i = 0; i < 4; i++) {
            unsigned mm = m[r][i];
            while (mm) {                                   // warp-uniform
                int src = __ffs(mm) - 1;
                mm &= mm - 1;
                float pv = __shfl_sync(0xffffffffu, xs[r][i], src);
                h0 += fmaxf(c[0] - pv, 0.0f);
                h1 += fmaxf(c[1] - pv, 0.0f);
                h0 += fmaxf(c[2] - pv, 0.0f);
                h1 += fmaxf(c[3] - pv, 0.0f);
            }
        }
    }

    // One MUFU log per thread (prod0*prod1 <= 2^16: fp32-safe)
    float bce = (base0 + base1) + __logf(prod0 * prod1);
    float v = 0.7f * bce + 0.3f * (h0 + h1);

    // ---- Warp reduce ----
#pragma unroll
    for (int o = 16; o > 0; o >>= 1)
        v += __shfl_xor_sync(0xffffffffu, v, o);
    if (lane == 0) s_warp[wid] = v;
    __syncthreads();

    // ---- Block reduce (warp 0) + exact fixed-point atomic accumulate ----
    if (wid == 0) {
        float s = (lane < WARPS_PER_BLOCK) ? s_warp[lane] : 0.0f;
#pragma unroll
        for (int o = 16; o > 0; o >>= 1)
            s += __shfl_xor_sync(0xffffffffu, s, o);
        if (lane == 0) {
            // s >= 0; 2^32 fixed-point: exact integer accumulation => deterministic
            unsigned long long q =
                (unsigned long long)__double2ll_rn((double)s * 4294967296.0);
            atomicAdd(&g_sum, q);
            int t = atomicAdd(&g_ticket, 1);
            if (t == N_BLOCKS - 1) {
                unsigned long long total = atomicAdd(&g_sum, 0ULL);
                double d = (double)(long long)total * (1.0 / 4294967296.0);
                out[0] = (float)(d / ((double)V_DIM * (double)N_ROWS));
                g_sum = 0ULL;     // reset for next graph replay
                g_ticket = 0;
            }
        }
    }
}

extern "C" void kernel_launch(void* const* d_in, const int* in_sizes, int n_in,
                              void* d_out, int out_size)
{
    const float* logits  = (const float*)d_in[0];
    const float* targets = (const float*)d_in[1];
    float* out = (float*)d_out;

    fused_loss_kernel<<<N_BLOCKS, THREADS_PER_BLOCK>>>(logits, targets, out);
}